// round 6
// baseline (speedup 1.0000x reference)
#include <cuda_runtime.h>
#include <cstdint>

#define SEQ 2048
#define NB 64
#define NF 16
#define HD 512
#define SLOT_PAD 516                     // 129 16B-units/row: stride ≡1 mod 8 -> conflict-free
#define SLOT_BYTES (NF * SLOT_PAD * 4)   // 33024
#define U_TOK 32                         // tokens per unit (block)
#define W_TOK 16                         // tokens per warp
#define STAGE_B 2048                     // 16 tok x 32 d x 4B
#define NW 8                             // warps/block: 4 d-quarters x 2 token-halves
#define SMEM_TOTAL (SLOT_BYTES + NW * 2 * STAGE_B)  // 65792 -> 3 blocks/SM
#define N_UNITS ((SEQ / U_TOK) * NB)     // 4096, x-major: u = x*64 + b
#define GRID_X 444                       // 3/SM x 148 SM: single wave

// Scratch (allocation-free rule: __device__ globals)
__device__ int g_list[NB * SEQ];   // packed: token_pos | (seg << 16), compacted per batch
__device__ int g_cnt[NB];

__device__ __forceinline__ unsigned long long ffma2(unsigned long long a,
                                                    unsigned long long b,
                                                    unsigned long long c) {
    unsigned long long d;
    asm("fma.rn.f32x2 %0, %1, %2, %3;" : "=l"(d) : "l"(a), "l"(b), "l"(c));
    return d;
}

__device__ __forceinline__ void cp16(void* dst_smem, const void* src) {
    unsigned saddr = (unsigned)__cvta_generic_to_shared(dst_smem);
    asm volatile("cp.async.cg.shared.global [%0], [%1], 16;" :: "r"(saddr), "l"(src));
}
__device__ __forceinline__ void cp_commit() {
    asm volatile("cp.async.commit_group;");
}
template <int N>
__device__ __forceinline__ void cp_wait() {
    asm volatile("cp.async.wait_group %0;" :: "n"(N));
}

// stage smem swizzle: 16B-unit address for (token t in 0..15, chunk c in 0..7).
// bank = (c + t) & 7: stores (lanes = 8 t-groups x 4 c-groups) hit each bank
// exactly 4x (minimal wavefronts); reads (4 distinct t, fixed c) conflict-free.
__device__ __forceinline__ int sw16(int t, int c) {
    return t * 8 + ((c + (t & 7)) & 7);
}

// ---------------------------------------------------------------------------
// Block-wide exclusive scan over 256 threads
// ---------------------------------------------------------------------------
__device__ __forceinline__ int block_exscan(int v, int* sh) {
    int lane = threadIdx.x & 31;
    int w = threadIdx.x >> 5;
    int incl = v;
#pragma unroll
    for (int o = 1; o < 32; o <<= 1) {
        int n = __shfl_up_sync(0xFFFFFFFFu, incl, o);
        if (lane >= o) incl += n;
    }
    if (lane == 31) sh[w] = incl;
    __syncthreads();
    if (threadIdx.x < 8) {
        int x = sh[threadIdx.x];
#pragma unroll
        for (int o = 1; o < 8; o <<= 1) {
            int n = __shfl_up_sync(0xFFu, x, o);
            if (threadIdx.x >= (unsigned)o) x += n;
        }
        sh[threadIdx.x] = x;
    }
    __syncthreads();
    int wofs = (w == 0) ? 0 : sh[w - 1];
    return wofs + incl - v;
}

// ---------------------------------------------------------------------------
// Kernel 1 (fused): zero output (all 256 blocks) + per-batch span ids +
// compaction (first 64 blocks).
// ---------------------------------------------------------------------------
__global__ __launch_bounds__(256) void seg_zero_kernel(const int* __restrict__ labels,
                                                       const int* pB, const int* pI,
                                                       const int* pMS,
                                                       float* __restrict__ out,
                                                       int out_n) {
    {
        int tid = blockIdx.x * 256 + threadIdx.x;
        int nthreads = gridDim.x * 256;
        int n4 = out_n >> 2;
        float4 z = make_float4(0.f, 0.f, 0.f, 0.f);
        for (int i = tid; i < n4; i += nthreads)
            reinterpret_cast<float4*>(out)[i] = z;
        for (int i = (n4 << 2) + tid; i < out_n; i += nthreads)
            out[i] = 0.0f;
    }
    if (blockIdx.x >= NB) return;

    __shared__ int sh[8];
    int b = blockIdx.x;
    int t = threadIdx.x;
    int Bv = pB ? *pB : 1;
    int Iv = pI ? *pI : 2;
    int MS = pMS ? *pMS : 512;

    const int4* row = reinterpret_cast<const int4*>(labels + b * SEQ) + t * 2;
    int4 a = row[0];
    int4 c = row[1];
    int lab[8] = {a.x, a.y, a.z, a.w, c.x, c.y, c.z, c.w};

    int incl[8];
    int csum = 0;
#pragma unroll
    for (int i = 0; i < 8; i++) {
        csum += (lab[i] == Bv);
        incl[i] = csum;
    }
    int ex = block_exscan(csum, sh);

    int seg[8], vfl[8];
    int vtot = 0;
#pragma unroll
    for (int i = 0; i < 8; i++) {
        seg[i] = ex + incl[i] - 1;
        vfl[i] = ((lab[i] == Bv) || (lab[i] == Iv)) && seg[i] >= 0 && seg[i] < MS;
        vtot += vfl[i];
    }
    __syncthreads();
    int vex = block_exscan(vtot, sh);

    int pos = vex;
#pragma unroll
    for (int i = 0; i < 8; i++) {
        if (vfl[i]) {
            g_list[b * SEQ + pos] = (t * 8 + i) | (seg[i] << 16);
            pos++;
        }
    }
    if (t == 255) g_cnt[b] = vex + vtot;
}

// ---------------------------------------------------------------------------
// Kernel 2: warp-autonomous gather-projection, 24 warps/SM.
//
// Unit = 32 compacted tokens of batch b (u = x*64 + b, x-major). Block = 8
// warps: warp (q = w&3, h = w>>2) owns d-quarter q of tokens [16h, 16h+16).
// Warp streams its 16tok x 128d slice in 4 cp.async stages of 32 d through a
// private 2x2KB double buffer.
//
// Staging: lane (r4 = l>>2, qq = l&3) covers tokens {r4, r4+8}, chunks
// {qq, qq+4} -> 4 cp16/lane/stage, each instr ~8 rows x 64B.
//
// Compute: lane (tg = l>>3, fh = l&7) tiles 4 tokens x f={fh, fh+8}; per 16B
// chunk: 4 H + 2 S LDS (broadcast/conflict-free) -> 16 FFMA2. acc = 16 regs.
// Quarter-d partial sums scatter via atomicAdd.
// ---------------------------------------------------------------------------
__global__ __launch_bounds__(256, 3) void proj_kernel(const float* __restrict__ hidden,
                                                      const float* __restrict__ slot,
                                                      const int* pMS,
                                                      float* __restrict__ out) {
    extern __shared__ float smem[];
    float* slot_sh = smem;
    char* ring = reinterpret_cast<char*>(smem) + SLOT_BYTES;
    int MS = pMS ? *pMS : 512;

    // stage slot_embs transposed: slot_sh[f][d]
    for (int i = threadIdx.x; i < HD * NF; i += 256) {
        int d = i >> 4;
        int f = i & 15;
        slot_sh[f * SLOT_PAD + d] = slot[i];
    }
    __syncthreads();

    int w = threadIdx.x >> 5;
    int lane = threadIdx.x & 31;
    int q = w & 3;            // d-quarter
    int h = w >> 2;           // token half
    char* buf0 = ring + w * 2 * STAGE_B;
    char* buf1 = buf0 + STAGE_B;

    int r4 = lane >> 2;       // staging token group (0..7)
    int qq = lane & 3;        // staging chunk quad (0..3)
    int tg = lane >> 3;       // compute token group (0..3)
    int fh = lane & 7;        // compute f half (0..7)

    // staging smem byte-offsets (unit-invariant): tokens r4+8m, chunks qq+4cc
    int dst16[2][2];
#pragma unroll
    for (int m = 0; m < 2; m++) {
        dst16[m][0] = sw16(r4 + 8 * m, qq) * 16;
        dst16[m][1] = sw16(r4 + 8 * m, qq + 4) * 16;
    }

    const float* sp0 = slot_sh + fh * SLOT_PAD + q * 128;
    const float* sp1 = slot_sh + (fh + 8) * SLOT_PAD + q * 128;
    const char* hbase = reinterpret_cast<const char*>(hidden) + q * 512;  // quarter offset in bytes

    for (int u = blockIdx.x; u < N_UNITS; u += GRID_X) {
        int x = u >> 6;
        int b = u & 63;
        int cnt = g_cnt[b];
        if (x * U_TOK >= cnt) continue;     // uniform across block
        int t0 = x * U_TOK + h * W_TOK;     // this warp's first compacted token

        // 32-bit byte offsets of this lane's two staged token rows (clamped)
        unsigned ofs[2];
#pragma unroll
        for (int m = 0; m < 2; m++) {
            int ti = t0 + r4 + 8 * m;
            if (ti >= cnt) ti = cnt - 1;
            unsigned s = (unsigned)(g_list[b * SEQ + ti] & 0xFFFF);
            ofs[m] = ((unsigned)b * SEQ + s) * (HD * 4);
        }

        auto issue = [&](int s, char* buf) {
#pragma unroll
            for (int m = 0; m < 2; m++) {
                const char* src = hbase + ofs[m] + s * 128;
                cp16(buf + dst16[m][0], src + qq * 16);
                cp16(buf + dst16[m][1], src + (qq + 4) * 16);
            }
            cp_commit();
        };

        unsigned long long acc[4][2];
#pragma unroll
        for (int j = 0; j < 4; j++) {
            acc[j][0] = 0ull;
            acc[j][1] = 0ull;
        }

        auto comp = [&](int s, const char* buf) {
#pragma unroll
            for (int c = 0; c < 8; c++) {
                ulonglong2 S0 = *reinterpret_cast<const ulonglong2*>(sp0 + s * 32 + c * 4);
                ulonglong2 S1 = *reinterpret_cast<const ulonglong2*>(sp1 + s * 32 + c * 4);
#pragma unroll
                for (int j = 0; j < 4; j++) {
                    int t = 4 * tg + j;
                    ulonglong2 H = *reinterpret_cast<const ulonglong2*>(buf + sw16(t, c) * 16);
                    acc[j][0] = ffma2(H.x, S0.x, acc[j][0]);
                    acc[j][0] = ffma2(H.y, S0.y, acc[j][0]);
                    acc[j][1] = ffma2(H.x, S1.x, acc[j][1]);
                    acc[j][1] = ffma2(H.y, S1.y, acc[j][1]);
                }
            }
        };

        issue(0, buf0);
        issue(1, buf1);
        cp_wait<1>();
        __syncwarp();
        comp(0, buf0);
        issue(2, buf0);
        cp_wait<1>();
        __syncwarp();
        comp(1, buf1);
        issue(3, buf1);
        cp_wait<1>();
        __syncwarp();
        comp(2, buf0);
        cp_wait<0>();
        __syncwarp();
        comp(3, buf1);

        // scatter quarter-d partial sums
#pragma unroll
        for (int j = 0; j < 4; j++) {
            int ti = t0 + 4 * tg + j;
            if (ti >= cnt) continue;
            int p = g_list[b * SEQ + ti];
            float* op = out + ((size_t)b * MS + (p >> 16)) * NF;
            float2 v0 = *reinterpret_cast<float2*>(&acc[j][0]);
            float2 v1 = *reinterpret_cast<float2*>(&acc[j][1]);
            atomicAdd(op + fh, v0.x + v0.y);
            atomicAdd(op + fh + 8, v1.x + v1.y);
        }
        __syncwarp();  // buffers free before next unit overwrites
    }
}

// ---------------------------------------------------------------------------
extern "C" void kernel_launch(void* const* d_in, const int* in_sizes, int n_in,
                              void* d_out, int out_size) {
    const float* hidden = (const float*)d_in[0];
    const float* slot = (const float*)d_in[1];
    const int* labels = (const int*)d_in[2];
    const int* pB = (n_in > 3) ? (const int*)d_in[3] : nullptr;
    const int* pI = (n_in > 4) ? (const int*)d_in[4] : nullptr;
    const int* pMS = (n_in > 5) ? (const int*)d_in[5] : nullptr;
    float* out = (float*)d_out;

    static bool attr_set = false;
    if (!attr_set) {
        cudaFuncSetAttribute(proj_kernel, cudaFuncAttributeMaxDynamicSharedMemorySize,
                             SMEM_TOTAL);
        attr_set = true;
    }

    seg_zero_kernel<<<256, 256>>>(labels, pB, pI, pMS, out, out_size);
    proj_kernel<<<GRID_X, 256, SMEM_TOTAL>>>(hidden, slot, pMS, out);
}